// round 13
// baseline (speedup 1.0000x reference)
#include <cuda_runtime.h>
#include <cstdint>

#define NN 8192
#define DD 64
#define EE 16384
#define NEGV -1e10f
#define TINYF 1.17549435e-38f

#define SEL_THREADS 256
#define TILE_J 128
#define TILE_STRIDE 68          // floats; 272B rows -> 16B aligned, LDS.128 conflict-free
#define NCHUNK (NN / TILE_J)    // 64
#define CAND_TILE 32
#define NMASKW 256              // 8192 bits
#define HASH_SZ 2048
#define HASH_CAP 1536
#define EMPTYK 0xFFFFFFFFFFFFFFFFull

// ---------------- scratch ----------------
__device__ float g_queries[NN * DD];
__device__ float g_qn[NN];
__device__ float g_hn[NN];
__device__ uint32_t g_gensmask[NMASKW];
__device__ int   g_glist[NN];
__device__ int   g_flag[NN];
__device__ unsigned long long g_best[NN];
__device__ int   g_newsend[NN];
__device__ int   g_newrec[NN];
__device__ int   g_ngens;
__device__ int   g_eactive;
__device__ int   g_ncand;

// ---------------- threefry2x32 (JAX-exact) ----------------
__host__ __device__ __forceinline__ void threefry2x32(uint32_t k0, uint32_t k1,
                                                      uint32_t x0, uint32_t x1,
                                                      uint32_t* o0, uint32_t* o1) {
  uint32_t ks2 = k0 ^ k1 ^ 0x1BD11BDAu;
#define ROTL32(v, r) (((v) << (r)) | ((v) >> (32 - (r))))
#define TFRND(r) { x0 += x1; x1 = ROTL32(x1, r); x1 ^= x0; }
  x0 += k0; x1 += k1;
  TFRND(13) TFRND(15) TFRND(26) TFRND(6)
  x0 += k1; x1 += ks2 + 1u;
  TFRND(17) TFRND(29) TFRND(16) TFRND(24)
  x0 += ks2; x1 += k0 + 2u;
  TFRND(13) TFRND(15) TFRND(26) TFRND(6)
  x0 += k0; x1 += k1 + 3u;
  TFRND(17) TFRND(29) TFRND(16) TFRND(24)
  x0 += k1; x1 += ks2 + 4u;
  TFRND(13) TFRND(15) TFRND(26) TFRND(6)
  x0 += ks2; x1 += k0 + 5u;
  *o0 = x0; *o1 = x1;
#undef TFRND
#undef ROTL32
}

__device__ __forceinline__ uint32_t random_bits32(uint32_t k0, uint32_t k1,
                                                  unsigned long long idx) {
  uint32_t o0, o1;
  threefry2x32(k0, k1, (uint32_t)(idx >> 32), (uint32_t)idx, &o0, &o1);
  return o0 ^ o1;
}

__device__ __forceinline__ float u01_from_bits(uint32_t bits) {
  return __uint_as_float((bits >> 9) | 0x3f800000u) - 1.0f;
}

// XLA ErfInv (Giles)
__device__ __forceinline__ float xla_erfinv(float x) {
  float w = -log1pf(-x * x);
  float p;
  if (w < 5.f) {
    w -= 2.5f;
    p = 2.81022636e-08f;
    p = fmaf(p, w, 3.43273939e-07f);
    p = fmaf(p, w, -3.5233877e-06f);
    p = fmaf(p, w, -4.39150654e-06f);
    p = fmaf(p, w, 0.00021858087f);
    p = fmaf(p, w, -0.00125372503f);
    p = fmaf(p, w, -0.00417768164f);
    p = fmaf(p, w, 0.246640727f);
    p = fmaf(p, w, 1.50140941f);
  } else {
    w = sqrtf(w) - 3.f;
    p = -0.000200214257f;
    p = fmaf(p, w, 0.000100950558f);
    p = fmaf(p, w, 0.00134934322f);
    p = fmaf(p, w, -0.00367342844f);
    p = fmaf(p, w, 0.00573950773f);
    p = fmaf(p, w, -0.0076224613f);
    p = fmaf(p, w, 0.00943887047f);
    p = fmaf(p, w, 1.00167406f);
    p = fmaf(p, w, 2.83297682f);
  }
  return p * x;
}

__device__ __forceinline__ unsigned long long enc_key(float v, int j) {
  uint32_t u = __float_as_uint(v);
  u = (u & 0x80000000u) ? ~u : (u | 0x80000000u);
  return ((unsigned long long)u << 32) | (unsigned long long)(0xFFFFFFFFu - (uint32_t)j);
}

__device__ __forceinline__ int warp_incl_scan(int v, int lane) {
#pragma unroll
  for (int d = 1; d < 32; d <<= 1) {
    int o = __shfl_up_sync(0xffffffffu, v, d);
    if (lane >= d) v += o;
  }
  return v;
}

// ---------- Kernel A: prep + generator bitmask ----------
__global__ void __launch_bounds__(512) k_prep(const float* __restrict__ nodes,
                                              const float* __restrict__ Wq,
                                              const float* __restrict__ bq,
                                              const float* __restrict__ Wp,
                                              const float* __restrict__ bp,
                                              const float* __restrict__ active_nodes,
                                              uint32_t kp0, uint32_t kp1) {
  __shared__ __align__(16) float sWq[DD * DD];
  __shared__ float sbq[DD];
  __shared__ float sWp[DD];
  __shared__ int   sgen[64];
  const int tid = threadIdx.x;
  const int warp = tid >> 5, lane = tid & 31;
  {
    const float4* w4 = reinterpret_cast<const float4*>(Wq);
    float4* s4 = reinterpret_cast<float4*>(sWq);
#pragma unroll
    for (int r = 0; r < 2; r++) s4[tid + (r << 9)] = w4[tid + (r << 9)];
    if (tid < DD) { sbq[tid] = bq[tid]; sWp[tid] = Wp[tid]; }
  }
  const int ibase = (blockIdx.x << 6) + (warp << 2);
  float2 n2r[4];
#pragma unroll
  for (int r = 0; r < 4; r++)
    n2r[r] = reinterpret_cast<const float2*>(nodes + (ibase + r) * DD)[lane];
  float anr[4];
#pragma unroll
  for (int r = 0; r < 4; r++) anr[r] = active_nodes[ibase + r];
  __syncthreads();
  const float2 b2 = reinterpret_cast<const float2*>(sbq)[lane];
  const float2 wp2 = reinterpret_cast<const float2*>(sWp)[lane];
  const float bp0 = bp[0];
#pragma unroll
  for (int r = 0; r < 4; r++) {
    const int i = ibase + r;
    const float2 n2 = n2r[r];
    float q0 = b2.x, q1 = b2.y;
#pragma unroll
    for (int k = 0; k < DD; k++) {
      float nk = __shfl_sync(0xffffffffu, (k & 1) ? n2.y : n2.x, k >> 1);
      float2 w = reinterpret_cast<const float2*>(sWq + k * DD)[lane];
      q0 = fmaf(nk, w.x, q0);
      q1 = fmaf(nk, w.y, q1);
    }
    reinterpret_cast<float2*>(g_queries + i * DD)[lane] = make_float2(q0, q1);
    float rq = q0 * q0 + q1 * q1;
    float rh = n2.x * n2.x + n2.y * n2.y;
    float rp = n2.x * wp2.x + n2.y * wp2.y;
#pragma unroll
    for (int d = 16; d > 0; d >>= 1) {
      rq += __shfl_xor_sync(0xffffffffu, rq, d);
      rh += __shfl_xor_sync(0xffffffffu, rh, d);
      rp += __shfl_xor_sync(0xffffffffu, rp, d);
    }
    if (lane == 0) {
      g_qn[i] = rq;
      g_hn[i] = rh;
      float z = rp + bp0;
      float prob = 0.5f * tanhf(0.5f * z) + 0.5f;   // XLA logistic
      uint32_t bits = random_bits32(kp0, kp1, (unsigned long long)i);
      float u = u01_from_bits(bits);
      sgen[(warp << 2) + r] = (u < prob * anr[r]) ? 1 : 0;
      g_best[i] = 0ull;
    }
  }
  __syncthreads();
  if (tid < 2) {
    uint32_t w = 0;
#pragma unroll
    for (int k = 0; k < 32; k++) w |= (uint32_t)sgen[(tid << 5) + k] << k;
    g_gensmask[(blockIdx.x << 1) + tid] = w;
  }
}

// ---------- Kernel B: select — row-in-registers, qsh-broadcast scoring ----------
__global__ void __launch_bounds__(SEL_THREADS) k_select(const float* __restrict__ nodes,
                                                        const float* __restrict__ active_nodes,
                                                        uint32_t ks0, uint32_t ks1) {
  __shared__ __align__(16) float sh[TILE_J * TILE_STRIDE];
  __shared__ __align__(16) float qsh[CAND_TILE * DD];
  __shared__ float s_qn[CAND_TILE];
  __shared__ int   s_ii[CAND_TILE];
  __shared__ int   s_glist[CAND_TILE];
  __shared__ int   s_wsum[8];
  const int tid = threadIdx.x;
  const int lane = tid & 31;
  const int wid = tid >> 5;
  const int jj = tid & 127;
  const int grp2 = tid >> 7;

  const uint32_t mw = g_gensmask[tid];
  const int cnt = __popc(mw);
  int incl = warp_incl_scan(cnt, lane);
  if (lane == 31) s_wsum[wid] = incl;
  __syncthreads();
  int wbase = 0, ncand = 0;
#pragma unroll
  for (int w = 0; w < 8; w++) {
    int v = s_wsum[w];
    if (w < wid) wbase += v;
    ncand += v;
  }
  const int mypre = wbase + incl - cnt;

  const int ng = (ncand + CAND_TILE - 1) / CAND_TILE;
  const int total = NCHUNK * ng;
  for (int w = blockIdx.x; w < total; w += gridDim.x) {
    const int chunk = w / ng;
    const int grp = w - chunk * ng;
    const int c0 = grp * CAND_TILE;
    const int jbase = chunk << 7;
    if (cnt) {
      uint32_t m = mw;
      int r = mypre;
      while (m) {
        int b = __ffs((int)m) - 1;
        if (r >= c0 && r < c0 + CAND_TILE) s_glist[r - c0] = (tid << 5) + b;
        m &= m - 1;
        r++;
      }
    }
    __syncthreads();
    {
      const float4* src = reinterpret_cast<const float4*>(nodes + (jbase << 6));
#pragma unroll
      for (int s = 0; s < 8; s++) {
        int idx4 = (s << 8) + tid;
        int row = idx4 >> 4, col4 = idx4 & 15;
        reinterpret_cast<float4*>(sh + row * TILE_STRIDE)[col4] = src[idx4];
      }
    }
    if (tid < CAND_TILE) {
      int idx = c0 + tid;
      int i = (idx < ncand) ? s_glist[tid] : 0;
      s_ii[tid] = i;
      s_qn[tid] = g_qn[i];
    }
#pragma unroll
    for (int s = 0; s < 2; s++) {
      int t4 = (s << 8) + tid;
      int c = t4 >> 4, k4 = t4 & 15;
      int idx = c0 + c;
      float4 qv = (idx < ncand)
          ? reinterpret_cast<const float4*>(g_queries + s_glist[c] * DD)[k4]
          : make_float4(0.f, 0.f, 0.f, 0.f);
      reinterpret_cast<float4*>(qsh + c * DD)[k4] = qv;
    }
    __syncthreads();
    const int j = jbase + jj;
    const float hn = g_hn[j];
    const float act = active_nodes[j];
    // one-time crossbar cost: copy this thread's row into registers
    float4 r4[16];
    {
      const float4* rowf4 = reinterpret_cast<const float4*>(sh + jj * TILE_STRIDE);
#pragma unroll
      for (int kk = 0; kk < 16; kk++) r4[kk] = rowf4[kk];
    }
    const int clim = (ncand - c0 < CAND_TILE) ? (ncand - c0) : CAND_TILE;
    const int cbeg = grp2 << 4;
    const int cend = (cbeg + 16 < clim) ? cbeg + 16 : clim;
    for (int c = cbeg; c < cend; c++) {
      const int i = s_ii[c];
      const float4* qf4 = reinterpret_cast<const float4*>(qsh + c * DD);  // warp-uniform -> broadcast
      float ax = 0.f, ay = 0.f, az = 0.f, aw = 0.f;
#pragma unroll
      for (int kk = 0; kk < 16; kk++) {
        float4 q = qf4[kk];
        ax = fmaf(q.x, r4[kk].x, ax);
        ay = fmaf(q.y, r4[kk].y, ay);
        az = fmaf(q.z, r4[kk].z, az);
        aw = fmaf(q.w, r4[kk].w, aw);
      }
      float num = (ax + az) + (ay + aw);
      float sc = num / (sqrtf(s_qn[c] * hn) + 1e-8f);
      sc = fminf(fmaxf(sc, -10000.f), 10000.f);
      if (act <= 0.f) sc = NEGV;
      if (j == i) sc = NEGV;
      unsigned long long lin = (unsigned long long)i * NN + (unsigned long long)j;
      uint32_t bits = random_bits32(ks0, ks1, lin);
      float u = fmaxf(TINYF, u01_from_bits(bits) + TINYF);
      float g = -logf(-logf(u));
      unsigned long long key = enc_key(sc + g, j);
#pragma unroll
      for (int d = 16; d > 0; d >>= 1) {
        unsigned long long o = __shfl_xor_sync(0xffffffffu, key, d);
        if (o > key) key = o;
      }
      if (lane == 0) atomicMax(&g_best[i], key);
    }
    __syncthreads();
  }
}

// ---- Kernel C: e_active + glist + exist-hash + compaction, ONE block ----
__global__ void __launch_bounds__(1024) k_cc(const float* __restrict__ active_edges,
                                             const int* __restrict__ senders,
                                             const int* __restrict__ receivers) {
  __shared__ unsigned long long hkey[HASH_SZ];
  __shared__ int   hcid[HASH_SZ];
  __shared__ float swF[32];
  __shared__ int   swA[32];
  __shared__ int   pre[33];
  const int tid = threadIdx.x;  // 1024
  const int lane = tid & 31, wid = tid >> 5;

  {
    const float4* ae4 = reinterpret_cast<const float4*>(active_edges);
    float s = 0.f;
#pragma unroll
    for (int r = 0; r < 4; r++) {
      float4 v = ae4[tid + (r << 10)];
      s += v.x + v.y + v.z + v.w;
    }
#pragma unroll
    for (int d = 16; d > 0; d >>= 1) s += __shfl_xor_sync(0xffffffffu, s, d);
    if (lane == 0) swF[wid] = s;
  }
  const uint32_t mw = (tid < NMASKW) ? g_gensmask[tid] : 0u;
  const int cnt = __popc(mw);
  int incl = warp_incl_scan(cnt, lane);
  if (lane == 31) swA[wid] = incl;
  __syncthreads();
  if (tid == 0) {
    pre[0] = 0;
#pragma unroll
    for (int w = 0; w < 32; w++) pre[w + 1] = pre[w] + swA[w];
    g_ncand = pre[32];
    float t = 0.f;
#pragma unroll
    for (int w = 0; w < 32; w++) t += swF[w];
    g_eactive = (int)t;
  }
  __syncthreads();
  const int ncand = pre[32];
  {
    int r = pre[wid] + incl - cnt;
    uint32_t m = mw;
    while (m) {
      int b = __ffs((int)m) - 1;
      g_glist[r] = (tid << 5) + b;
      g_flag[r] = 1;
      m &= m - 1;
      r++;
    }
  }
  __syncthreads();

  if (ncand <= HASH_CAP) {
#pragma unroll
    for (int r = 0; r < HASH_SZ / 1024; r++) hkey[tid + (r << 10)] = EMPTYK;
    __syncthreads();
    for (int c = tid; c < ncand; c += 1024) {
      int i = g_glist[c];
      unsigned long long b = g_best[i];
      uint32_t sel = 0xFFFFFFFFu - (uint32_t)(b & 0xFFFFFFFFull);
      unsigned long long key = ((unsigned long long)(uint32_t)i << 32) | sel;
      uint32_t h = (uint32_t)((key * 0x9E3779B97F4A7C15ull) >> 40) & (HASH_SZ - 1);
      while (true) {
        unsigned long long prev = atomicCAS(&hkey[h], EMPTYK, key);
        if (prev == EMPTYK) { hcid[h] = c; break; }
        h = (h + 1) & (HASH_SZ - 1);
      }
    }
    __syncthreads();
    const int4* s4 = reinterpret_cast<const int4*>(senders);
    const int4* r4 = reinterpret_cast<const int4*>(receivers);
#pragma unroll
    for (int r = 0; r < EE / 4 / 1024; r++) {
      int idx4 = tid + (r << 10);
      int4 sv = s4[idx4];
      int4 rv = r4[idx4];
      const int ss[4] = {sv.x, sv.y, sv.z, sv.w};
      const int rr[4] = {rv.x, rv.y, rv.z, rv.w};
#pragma unroll
      for (int q = 0; q < 4; q++) {
        unsigned long long key =
            ((unsigned long long)(uint32_t)ss[q] << 32) | (uint32_t)rr[q];
        uint32_t h = (uint32_t)((key * 0x9E3779B97F4A7C15ull) >> 40) & (HASH_SZ - 1);
        while (true) {
          unsigned long long k = hkey[h];
          if (k == EMPTYK) break;
          if (k == key) { g_flag[hcid[h]] = 0; break; }
          h = (h + 1) & (HASH_SZ - 1);
        }
      }
    }
    __syncthreads();
  } else {
    for (int c = tid; c < ncand; c += 1024) {
      int i = g_glist[c];
      unsigned long long b = g_best[i];
      uint32_t sel = 0xFFFFFFFFu - (uint32_t)(b & 0xFFFFFFFFull);
      int found = 0;
      for (int e = 0; e < EE; e++)
        found |= (senders[e] == i && (uint32_t)receivers[e] == sel);
      if (found) g_flag[c] = 0;
    }
    __syncthreads();
  }

  int flags[8];
  int ccnt = 0;
#pragma unroll
  for (int r = 0; r < 8; r++) {
    int c = tid * 8 + r;
    flags[r] = (c < ncand) ? g_flag[c] : 0;
    ccnt += flags[r];
  }
  int cincl = warp_incl_scan(ccnt, lane);
  if (lane == 31) swA[wid] = cincl;
  __syncthreads();
  if (tid == 0) {
    pre[0] = 0;
#pragma unroll
    for (int w = 0; w < 32; w++) pre[w + 1] = pre[w] + swA[w];
    int total = pre[32];
    int allowed = EE - g_eactive - 1;
    int n = total < 0 ? 0 : total;
    if (n > allowed) n = allowed;
    g_ngens = n;
  }
  __syncthreads();
  int off = pre[wid] + cincl - ccnt;
#pragma unroll
  for (int r = 0; r < 8; r++) {
    int c = tid * 8 + r;
    if (flags[r]) {
      int i = g_glist[c];
      unsigned long long b = g_best[i];
      g_newsend[off] = i;
      g_newrec[off] = (int)(0xFFFFFFFFu - (uint32_t)(b & 0xFFFFFFFFull));
      off++;
    }
  }
}

// ---------- Kernel D: output writer — 1 float4/thread, full occupancy ----------
// Layout: [ new_edges (E*D f32) | nsend (E) | nrec (E) | naedges (E) ]
__global__ void __launch_bounds__(256) k_out(const float* __restrict__ edges,
                                             const int* __restrict__ senders,
                                             const int* __restrict__ receivers,
                                             float4* __restrict__ out,
                                             uint32_t ke0, uint32_t ke1, int out_size) {
  const int idx4 = blockIdx.x * 256 + threadIdx.x;
  const int base = idx4 << 2;
  if (base >= out_size) return;
  const int ngen = g_ngens;
  const int ea = g_eactive;
  const int T1 = EE * DD;
  float4 v;
  if (base < T1) {
    v = reinterpret_cast<const float4*>(edges)[idx4];
    int e = base >> 6;
    if (e >= ea && e < ea + ngen) {
      float* vp = reinterpret_cast<float*>(&v);
#pragma unroll
      for (int cmp = 0; cmp < 4; cmp++) {
        uint32_t bits = random_bits32(ke0, ke1, (unsigned long long)(base + cmp));
        float u01 = u01_from_bits(bits);
        const float lo = -0.99999994f;
        float uu = fmaxf(lo, fmaf(u01, 2.0f, lo));
        vp[cmp] += 1.41421356f * xla_erfinv(uu);
      }
    }
  } else if (base < T1 + EE) {
    float* vp = reinterpret_cast<float*>(&v);
#pragma unroll
    for (int cmp = 0; cmp < 4; cmp++) {
      int j = base + cmp - T1;
      float x;
      if (j < ea)             x = (float)senders[j];
      else if (j < ea + ngen) x = (float)g_newsend[j - ea];
      else                    x = (float)(NN - 1);
      vp[cmp] = x;
    }
  } else if (base < T1 + 2 * EE) {
    float* vp = reinterpret_cast<float*>(&v);
#pragma unroll
    for (int cmp = 0; cmp < 4; cmp++) {
      int j = base + cmp - T1 - EE;
      float x;
      if (j < ea)             x = (float)receivers[j];
      else if (j < ea + ngen) x = (float)g_newrec[j - ea];
      else                    x = (float)(NN - 1);
      vp[cmp] = x;
    }
  } else {
    float* vp = reinterpret_cast<float*>(&v);
#pragma unroll
    for (int cmp = 0; cmp < 4; cmp++) {
      int j = base + cmp - T1 - 2 * EE;
      vp[cmp] = (j < ea + ngen && j >= 0) ? 1.0f : 0.0f;
    }
  }
  if (base + 4 <= out_size) {
    out[idx4] = v;
  } else {
    float* vp = reinterpret_cast<float*>(&v);
    float* os = reinterpret_cast<float*>(out);
    for (int cmp = 0; cmp < out_size - base; cmp++) os[base + cmp] = vp[cmp];
  }
}

// ---------------- host ----------------
extern "C" void kernel_launch(void* const* d_in, const int* in_sizes, int n_in,
                              void* d_out, int out_size) {
  const float* nodes        = (const float*)d_in[0];
  const float* edges        = (const float*)d_in[1];
  const int*   receivers    = (const int*)d_in[2];
  const int*   senders      = (const int*)d_in[3];
  const float* active_nodes = (const float*)d_in[4];
  const float* active_edges = (const float*)d_in[5];
  const float* Wq           = (const float*)d_in[6];
  const float* bq           = (const float*)d_in[7];
  const float* Wp           = (const float*)d_in[8];
  const float* bp           = (const float*)d_in[9];
  (void)in_sizes; (void)n_in;

  const uint32_t K0 = 0u, K1 = 42u;
  uint32_t kp0, kp1, ke0, ke1, ks0, ks1;
  threefry2x32(K0, K1, 0u, 0u, &kp0, &kp1);  // key_prob
  threefry2x32(K0, K1, 0u, 1u, &ke0, &ke1);  // key_edges
  threefry2x32(K0, K1, 0u, 2u, &ks0, &ks1);  // key_samp

  k_prep<<<NN / 64, 512>>>(nodes, Wq, bq, Wp, bp, active_nodes, kp0, kp1);
  k_select<<<592, SEL_THREADS>>>(nodes, active_nodes, ks0, ks1);
  k_cc<<<1, 1024>>>(active_edges, senders, receivers);

  int n4 = (out_size + 3) >> 2;
  int blocks = (n4 + 255) / 256;
  k_out<<<blocks, 256>>>(edges, senders, receivers, (float4*)d_out, ke0, ke1, out_size);
}

// round 14
// speedup vs baseline: 1.5783x; 1.5783x over previous
#include <cuda_runtime.h>
#include <cstdint>

#define NN 8192
#define DD 64
#define EE 16384
#define NEGV -1e10f
#define TINYF 1.17549435e-38f

#define SEL_THREADS 256
#define TILE_J 128
#define TILE_STRIDE 68          // floats; 272B rows -> 16B aligned, LDS.128 conflict-free
#define NCHUNK (NN / TILE_J)    // 64
#define CAND_TILE 32
#define NMASKW 256              // 8192 bits
#define HASH_SZ 2048
#define HASH_CAP 1536
#define EMPTYK 0xFFFFFFFFFFFFFFFFull

// ---------------- scratch ----------------
__device__ float g_queries[NN * DD];
__device__ float g_qn[NN];
__device__ float g_hn[NN];
__device__ uint32_t g_gensmask[NMASKW];
__device__ int   g_glist[NN];
__device__ int   g_flag[NN];
__device__ unsigned long long g_best[NN];
__device__ int   g_newsend[NN];
__device__ int   g_newrec[NN];
__device__ int   g_ngens;
__device__ int   g_eactive;
__device__ int   g_ncand;

// ---------------- threefry2x32 (JAX-exact) ----------------
__host__ __device__ __forceinline__ void threefry2x32(uint32_t k0, uint32_t k1,
                                                      uint32_t x0, uint32_t x1,
                                                      uint32_t* o0, uint32_t* o1) {
  uint32_t ks2 = k0 ^ k1 ^ 0x1BD11BDAu;
#define ROTL32(v, r) (((v) << (r)) | ((v) >> (32 - (r))))
#define TFRND(r) { x0 += x1; x1 = ROTL32(x1, r); x1 ^= x0; }
  x0 += k0; x1 += k1;
  TFRND(13) TFRND(15) TFRND(26) TFRND(6)
  x0 += k1; x1 += ks2 + 1u;
  TFRND(17) TFRND(29) TFRND(16) TFRND(24)
  x0 += ks2; x1 += k0 + 2u;
  TFRND(13) TFRND(15) TFRND(26) TFRND(6)
  x0 += k0; x1 += k1 + 3u;
  TFRND(17) TFRND(29) TFRND(16) TFRND(24)
  x0 += k1; x1 += ks2 + 4u;
  TFRND(13) TFRND(15) TFRND(26) TFRND(6)
  x0 += ks2; x1 += k0 + 5u;
  *o0 = x0; *o1 = x1;
#undef TFRND
#undef ROTL32
}

__device__ __forceinline__ uint32_t random_bits32(uint32_t k0, uint32_t k1,
                                                  unsigned long long idx) {
  uint32_t o0, o1;
  threefry2x32(k0, k1, (uint32_t)(idx >> 32), (uint32_t)idx, &o0, &o1);
  return o0 ^ o1;
}

__device__ __forceinline__ float u01_from_bits(uint32_t bits) {
  return __uint_as_float((bits >> 9) | 0x3f800000u) - 1.0f;
}

// XLA ErfInv (Giles)
__device__ __forceinline__ float xla_erfinv(float x) {
  float w = -log1pf(-x * x);
  float p;
  if (w < 5.f) {
    w -= 2.5f;
    p = 2.81022636e-08f;
    p = fmaf(p, w, 3.43273939e-07f);
    p = fmaf(p, w, -3.5233877e-06f);
    p = fmaf(p, w, -4.39150654e-06f);
    p = fmaf(p, w, 0.00021858087f);
    p = fmaf(p, w, -0.00125372503f);
    p = fmaf(p, w, -0.00417768164f);
    p = fmaf(p, w, 0.246640727f);
    p = fmaf(p, w, 1.50140941f);
  } else {
    w = sqrtf(w) - 3.f;
    p = -0.000200214257f;
    p = fmaf(p, w, 0.000100950558f);
    p = fmaf(p, w, 0.00134934322f);
    p = fmaf(p, w, -0.00367342844f);
    p = fmaf(p, w, 0.00573950773f);
    p = fmaf(p, w, -0.0076224613f);
    p = fmaf(p, w, 0.00943887047f);
    p = fmaf(p, w, 1.00167406f);
    p = fmaf(p, w, 2.83297682f);
  }
  return p * x;
}

__device__ __forceinline__ unsigned long long enc_key(float v, int j) {
  uint32_t u = __float_as_uint(v);
  u = (u & 0x80000000u) ? ~u : (u | 0x80000000u);
  return ((unsigned long long)u << 32) | (unsigned long long)(0xFFFFFFFFu - (uint32_t)j);
}

__device__ __forceinline__ int warp_incl_scan(int v, int lane) {
#pragma unroll
  for (int d = 1; d < 32; d <<= 1) {
    int o = __shfl_up_sync(0xffffffffu, v, d);
    if (lane >= d) v += o;
  }
  return v;
}

// ---------- Kernel A: prep + generator bitmask ----------
__global__ void __launch_bounds__(512) k_prep(const float* __restrict__ nodes,
                                              const float* __restrict__ Wq,
                                              const float* __restrict__ bq,
                                              const float* __restrict__ Wp,
                                              const float* __restrict__ bp,
                                              const float* __restrict__ active_nodes,
                                              uint32_t kp0, uint32_t kp1) {
  __shared__ __align__(16) float sWq[DD * DD];
  __shared__ float sbq[DD];
  __shared__ float sWp[DD];
  __shared__ int   sgen[64];
  const int tid = threadIdx.x;
  const int warp = tid >> 5, lane = tid & 31;
  {
    const float4* w4 = reinterpret_cast<const float4*>(Wq);
    float4* s4 = reinterpret_cast<float4*>(sWq);
#pragma unroll
    for (int r = 0; r < 2; r++) s4[tid + (r << 9)] = w4[tid + (r << 9)];
    if (tid < DD) { sbq[tid] = bq[tid]; sWp[tid] = Wp[tid]; }
  }
  const int ibase = (blockIdx.x << 6) + (warp << 2);
  float2 n2r[4];
#pragma unroll
  for (int r = 0; r < 4; r++)
    n2r[r] = reinterpret_cast<const float2*>(nodes + (ibase + r) * DD)[lane];
  float anr[4];
#pragma unroll
  for (int r = 0; r < 4; r++) anr[r] = active_nodes[ibase + r];
  __syncthreads();
  const float2 b2 = reinterpret_cast<const float2*>(sbq)[lane];
  const float2 wp2 = reinterpret_cast<const float2*>(sWp)[lane];
  const float bp0 = bp[0];
#pragma unroll
  for (int r = 0; r < 4; r++) {
    const int i = ibase + r;
    const float2 n2 = n2r[r];
    float q0 = b2.x, q1 = b2.y;
#pragma unroll
    for (int k = 0; k < DD; k++) {
      float nk = __shfl_sync(0xffffffffu, (k & 1) ? n2.y : n2.x, k >> 1);
      float2 w = reinterpret_cast<const float2*>(sWq + k * DD)[lane];
      q0 = fmaf(nk, w.x, q0);
      q1 = fmaf(nk, w.y, q1);
    }
    reinterpret_cast<float2*>(g_queries + i * DD)[lane] = make_float2(q0, q1);
    float rq = q0 * q0 + q1 * q1;
    float rh = n2.x * n2.x + n2.y * n2.y;
    float rp = n2.x * wp2.x + n2.y * wp2.y;
#pragma unroll
    for (int d = 16; d > 0; d >>= 1) {
      rq += __shfl_xor_sync(0xffffffffu, rq, d);
      rh += __shfl_xor_sync(0xffffffffu, rh, d);
      rp += __shfl_xor_sync(0xffffffffu, rp, d);
    }
    if (lane == 0) {
      g_qn[i] = rq;
      g_hn[i] = rh;
      float z = rp + bp0;
      float prob = 0.5f * tanhf(0.5f * z) + 0.5f;   // XLA logistic
      uint32_t bits = random_bits32(kp0, kp1, (unsigned long long)i);
      float u = u01_from_bits(bits);
      sgen[(warp << 2) + r] = (u < prob * anr[r]) ? 1 : 0;
      g_best[i] = 0ull;
    }
  }
  __syncthreads();
  if (tid < 2) {
    uint32_t w = 0;
#pragma unroll
    for (int k = 0; k < 32; k++) w |= (uint32_t)sgen[(tid << 5) + k] << k;
    g_gensmask[(blockIdx.x << 1) + tid] = w;
  }
}

// ---------- Kernel B: select — derives its candidate window from the bitmask ----------
__global__ void __launch_bounds__(SEL_THREADS) k_select(const float* __restrict__ nodes,
                                                        const float* __restrict__ active_nodes,
                                                        uint32_t ks0, uint32_t ks1) {
  __shared__ __align__(16) float sh[TILE_J * TILE_STRIDE];
  __shared__ __align__(16) float qsh[CAND_TILE * DD];
  __shared__ float s_qn[CAND_TILE];
  __shared__ int   s_ii[CAND_TILE];
  __shared__ int   s_glist[CAND_TILE];
  __shared__ int   s_wsum[8];
  const int tid = threadIdx.x;
  const int lane = tid & 31;
  const int wid = tid >> 5;
  const int jj = tid & 127;
  const int grp2 = tid >> 7;

  const uint32_t mw = g_gensmask[tid];
  const int cnt = __popc(mw);
  int incl = warp_incl_scan(cnt, lane);
  if (lane == 31) s_wsum[wid] = incl;
  __syncthreads();
  int wbase = 0, ncand = 0;
#pragma unroll
  for (int w = 0; w < 8; w++) {
    int v = s_wsum[w];
    if (w < wid) wbase += v;
    ncand += v;
  }
  const int mypre = wbase + incl - cnt;

  const int ng = (ncand + CAND_TILE - 1) / CAND_TILE;
  const int total = NCHUNK * ng;
  for (int w = blockIdx.x; w < total; w += gridDim.x) {
    const int chunk = w / ng;
    const int grp = w - chunk * ng;
    const int c0 = grp * CAND_TILE;
    const int jbase = chunk << 7;
    if (cnt) {
      uint32_t m = mw;
      int r = mypre;
      while (m) {
        int b = __ffs((int)m) - 1;
        if (r >= c0 && r < c0 + CAND_TILE) s_glist[r - c0] = (tid << 5) + b;
        m &= m - 1;
        r++;
      }
    }
    __syncthreads();
    {
      const float4* src = reinterpret_cast<const float4*>(nodes + (jbase << 6));
#pragma unroll
      for (int s = 0; s < 8; s++) {
        int idx4 = (s << 8) + tid;
        int row = idx4 >> 4, col4 = idx4 & 15;
        reinterpret_cast<float4*>(sh + row * TILE_STRIDE)[col4] = src[idx4];
      }
    }
    if (tid < CAND_TILE) {
      int idx = c0 + tid;
      int i = (idx < ncand) ? s_glist[tid] : 0;
      s_ii[tid] = i;
      s_qn[tid] = g_qn[i];
    }
#pragma unroll
    for (int s = 0; s < 2; s++) {
      int t4 = (s << 8) + tid;
      int c = t4 >> 4, k4 = t4 & 15;
      int idx = c0 + c;
      float4 qv = (idx < ncand)
          ? reinterpret_cast<const float4*>(g_queries + s_glist[c] * DD)[k4]
          : make_float4(0.f, 0.f, 0.f, 0.f);
      reinterpret_cast<float4*>(qsh + c * DD)[k4] = qv;
    }
    __syncthreads();
    const int j = jbase + jj;
    const float hn = g_hn[j];
    const float act = active_nodes[j];
    const float4* rowf4 = reinterpret_cast<const float4*>(sh + jj * TILE_STRIDE);
    const int clim = (ncand - c0 < CAND_TILE) ? (ncand - c0) : CAND_TILE;
    const int cbeg = grp2 << 4;
    const int cend = (cbeg + 16 < clim) ? cbeg + 16 : clim;
    for (int c = cbeg; c < cend; c++) {
      const int i = s_ii[c];
      const float4* qf4 = reinterpret_cast<const float4*>(qsh + c * DD);
      float ax = 0.f, ay = 0.f, az = 0.f, aw = 0.f;
#pragma unroll
      for (int kk = 0; kk < 16; kk++) {
        float4 r = rowf4[kk];
        float4 q = qf4[kk];
        ax = fmaf(q.x, r.x, ax);
        ay = fmaf(q.y, r.y, ay);
        az = fmaf(q.z, r.z, az);
        aw = fmaf(q.w, r.w, aw);
      }
      float num = (ax + az) + (ay + aw);
      float sc = num / (sqrtf(s_qn[c] * hn) + 1e-8f);
      sc = fminf(fmaxf(sc, -10000.f), 10000.f);
      if (act <= 0.f) sc = NEGV;
      if (j == i) sc = NEGV;
      unsigned long long lin = (unsigned long long)i * NN + (unsigned long long)j;
      uint32_t bits = random_bits32(ks0, ks1, lin);
      float u = fmaxf(TINYF, u01_from_bits(bits) + TINYF);
      float g = -logf(-logf(u));
      unsigned long long key = enc_key(sc + g, j);
#pragma unroll
      for (int d = 16; d > 0; d >>= 1) {
        unsigned long long o = __shfl_xor_sync(0xffffffffu, key, d);
        if (o > key) key = o;
      }
      if (lane == 0) atomicMax(&g_best[i], key);
    }
    __syncthreads();
  }
}

// ---- Kernel C: e_active + glist + exist-hash + compaction, ONE block ----
__global__ void __launch_bounds__(1024) k_cc(const float* __restrict__ active_edges,
                                             const int* __restrict__ senders,
                                             const int* __restrict__ receivers) {
  __shared__ unsigned long long hkey[HASH_SZ];
  __shared__ int   hcid[HASH_SZ];
  __shared__ float swF[32];
  __shared__ int   swA[32];
  __shared__ int   pre[33];
  const int tid = threadIdx.x;  // 1024
  const int lane = tid & 31, wid = tid >> 5;

  {
    const float4* ae4 = reinterpret_cast<const float4*>(active_edges);
    float s = 0.f;
#pragma unroll
    for (int r = 0; r < 4; r++) {
      float4 v = ae4[tid + (r << 10)];
      s += v.x + v.y + v.z + v.w;
    }
#pragma unroll
    for (int d = 16; d > 0; d >>= 1) s += __shfl_xor_sync(0xffffffffu, s, d);
    if (lane == 0) swF[wid] = s;
  }
  const uint32_t mw = (tid < NMASKW) ? g_gensmask[tid] : 0u;
  const int cnt = __popc(mw);
  int incl = warp_incl_scan(cnt, lane);
  if (lane == 31) swA[wid] = incl;
  __syncthreads();
  if (tid == 0) {
    pre[0] = 0;
#pragma unroll
    for (int w = 0; w < 32; w++) pre[w + 1] = pre[w] + swA[w];
    g_ncand = pre[32];
    float t = 0.f;
#pragma unroll
    for (int w = 0; w < 32; w++) t += swF[w];
    g_eactive = (int)t;
  }
  __syncthreads();
  const int ncand = pre[32];
  {
    int r = pre[wid] + incl - cnt;
    uint32_t m = mw;
    while (m) {
      int b = __ffs((int)m) - 1;
      g_glist[r] = (tid << 5) + b;
      g_flag[r] = 1;
      m &= m - 1;
      r++;
    }
  }
  __syncthreads();

  if (ncand <= HASH_CAP) {
#pragma unroll
    for (int r = 0; r < HASH_SZ / 1024; r++) hkey[tid + (r << 10)] = EMPTYK;
    __syncthreads();
    for (int c = tid; c < ncand; c += 1024) {
      int i = g_glist[c];
      unsigned long long b = g_best[i];
      uint32_t sel = 0xFFFFFFFFu - (uint32_t)(b & 0xFFFFFFFFull);
      unsigned long long key = ((unsigned long long)(uint32_t)i << 32) | sel;
      uint32_t h = (uint32_t)((key * 0x9E3779B97F4A7C15ull) >> 40) & (HASH_SZ - 1);
      while (true) {
        unsigned long long prev = atomicCAS(&hkey[h], EMPTYK, key);
        if (prev == EMPTYK) { hcid[h] = c; break; }
        h = (h + 1) & (HASH_SZ - 1);
      }
    }
    __syncthreads();
    const int4* s4 = reinterpret_cast<const int4*>(senders);
    const int4* r4 = reinterpret_cast<const int4*>(receivers);
#pragma unroll
    for (int r = 0; r < EE / 4 / 1024; r++) {
      int idx4 = tid + (r << 10);
      int4 sv = s4[idx4];
      int4 rv = r4[idx4];
      const int ss[4] = {sv.x, sv.y, sv.z, sv.w};
      const int rr[4] = {rv.x, rv.y, rv.z, rv.w};
#pragma unroll
      for (int q = 0; q < 4; q++) {
        unsigned long long key =
            ((unsigned long long)(uint32_t)ss[q] << 32) | (uint32_t)rr[q];
        uint32_t h = (uint32_t)((key * 0x9E3779B97F4A7C15ull) >> 40) & (HASH_SZ - 1);
        while (true) {
          unsigned long long k = hkey[h];
          if (k == EMPTYK) break;
          if (k == key) { g_flag[hcid[h]] = 0; break; }
          h = (h + 1) & (HASH_SZ - 1);
        }
      }
    }
    __syncthreads();
  } else {
    for (int c = tid; c < ncand; c += 1024) {
      int i = g_glist[c];
      unsigned long long b = g_best[i];
      uint32_t sel = 0xFFFFFFFFu - (uint32_t)(b & 0xFFFFFFFFull);
      int found = 0;
      for (int e = 0; e < EE; e++)
        found |= (senders[e] == i && (uint32_t)receivers[e] == sel);
      if (found) g_flag[c] = 0;
    }
    __syncthreads();
  }

  int flags[8];
  int ccnt = 0;
#pragma unroll
  for (int r = 0; r < 8; r++) {
    int c = tid * 8 + r;
    flags[r] = (c < ncand) ? g_flag[c] : 0;
    ccnt += flags[r];
  }
  int cincl = warp_incl_scan(ccnt, lane);
  if (lane == 31) swA[wid] = cincl;
  __syncthreads();
  if (tid == 0) {
    pre[0] = 0;
#pragma unroll
    for (int w = 0; w < 32; w++) pre[w + 1] = pre[w] + swA[w];
    int total = pre[32];
    int allowed = EE - g_eactive - 1;
    int n = total < 0 ? 0 : total;
    if (n > allowed) n = allowed;
    g_ngens = n;
  }
  __syncthreads();
  int off = pre[wid] + cincl - ccnt;
#pragma unroll
  for (int r = 0; r < 8; r++) {
    int c = tid * 8 + r;
    if (flags[r]) {
      int i = g_glist[c];
      unsigned long long b = g_best[i];
      g_newsend[off] = i;
      g_newrec[off] = (int)(0xFFFFFFFFu - (uint32_t)(b & 0xFFFFFFFFull));
      off++;
    }
  }
}

// ---------- Kernel D: output writer — 1 float4/thread, full occupancy ----------
// Layout: [ new_edges (E*D f32) | nsend (E) | nrec (E) | naedges (E) ]
__global__ void __launch_bounds__(256) k_out(const float* __restrict__ edges,
                                             const int* __restrict__ senders,
                                             const int* __restrict__ receivers,
                                             float4* __restrict__ out,
                                             uint32_t ke0, uint32_t ke1, int out_size) {
  const int idx4 = blockIdx.x * 256 + threadIdx.x;
  const int base = idx4 << 2;
  if (base >= out_size) return;
  const int ngen = g_ngens;
  const int ea = g_eactive;
  const int T1 = EE * DD;
  float4 v;
  if (base < T1) {
    v = reinterpret_cast<const float4*>(edges)[idx4];
    int e = base >> 6;
    if (e >= ea && e < ea + ngen) {
      float* vp = reinterpret_cast<float*>(&v);
#pragma unroll
      for (int cmp = 0; cmp < 4; cmp++) {
        uint32_t bits = random_bits32(ke0, ke1, (unsigned long long)(base + cmp));
        float u01 = u01_from_bits(bits);
        const float lo = -0.99999994f;
        float uu = fmaxf(lo, fmaf(u01, 2.0f, lo));
        vp[cmp] += 1.41421356f * xla_erfinv(uu);
      }
    }
  } else if (base < T1 + EE) {
    float* vp = reinterpret_cast<float*>(&v);
#pragma unroll
    for (int cmp = 0; cmp < 4; cmp++) {
      int j = base + cmp - T1;
      float x;
      if (j < ea)             x = (float)senders[j];
      else if (j < ea + ngen) x = (float)g_newsend[j - ea];
      else                    x = (float)(NN - 1);
      vp[cmp] = x;
    }
  } else if (base < T1 + 2 * EE) {
    float* vp = reinterpret_cast<float*>(&v);
#pragma unroll
    for (int cmp = 0; cmp < 4; cmp++) {
      int j = base + cmp - T1 - EE;
      float x;
      if (j < ea)             x = (float)receivers[j];
      else if (j < ea + ngen) x = (float)g_newrec[j - ea];
      else                    x = (float)(NN - 1);
      vp[cmp] = x;
    }
  } else {
    float* vp = reinterpret_cast<float*>(&v);
#pragma unroll
    for (int cmp = 0; cmp < 4; cmp++) {
      int j = base + cmp - T1 - 2 * EE;
      vp[cmp] = (j < ea + ngen && j >= 0) ? 1.0f : 0.0f;
    }
  }
  if (base + 4 <= out_size) {
    out[idx4] = v;
  } else {
    float* vp = reinterpret_cast<float*>(&v);
    float* os = reinterpret_cast<float*>(out);
    for (int cmp = 0; cmp < out_size - base; cmp++) os[base + cmp] = vp[cmp];
  }
}

// ---------------- host ----------------
extern "C" void kernel_launch(void* const* d_in, const int* in_sizes, int n_in,
                              void* d_out, int out_size) {
  const float* nodes        = (const float*)d_in[0];
  const float* edges        = (const float*)d_in[1];
  const int*   receivers    = (const int*)d_in[2];
  const int*   senders      = (const int*)d_in[3];
  const float* active_nodes = (const float*)d_in[4];
  const float* active_edges = (const float*)d_in[5];
  const float* Wq           = (const float*)d_in[6];
  const float* bq           = (const float*)d_in[7];
  const float* Wp           = (const float*)d_in[8];
  const float* bp           = (const float*)d_in[9];
  (void)in_sizes; (void)n_in;

  const uint32_t K0 = 0u, K1 = 42u;
  uint32_t kp0, kp1, ke0, ke1, ks0, ks1;
  threefry2x32(K0, K1, 0u, 0u, &kp0, &kp1);  // key_prob
  threefry2x32(K0, K1, 0u, 1u, &ke0, &ke1);  // key_edges
  threefry2x32(K0, K1, 0u, 2u, &ks0, &ks1);  // key_samp

  k_prep<<<NN / 64, 512>>>(nodes, Wq, bq, Wp, bp, active_nodes, kp0, kp1);
  k_select<<<592, SEL_THREADS>>>(nodes, active_nodes, ks0, ks1);
  k_cc<<<1, 1024>>>(active_edges, senders, receivers);

  int n4 = (out_size + 3) >> 2;
  int blocks = (n4 + 255) / 256;
  k_out<<<blocks, 256>>>(edges, senders, receivers, (float4*)d_out, ke0, ke1, out_size);
}

// round 15
// speedup vs baseline: 1.6474x; 1.0437x over previous
#include <cuda_runtime.h>
#include <cstdint>

#define NN 8192
#define DD 64
#define EE 16384
#define NEGV -1e10f
#define TINYF 1.17549435e-38f

#define SEL_THREADS 256
#define TILE_J 128
#define TILE_STRIDE 68          // floats; 272B rows -> 16B aligned, LDS.128 conflict-free
#define NCHUNK (NN / TILE_J)    // 64
#define CAND_TILE 32
#define NMASKW 256              // 8192 bits
#define HASH_SZ 2048
#define HASH_CAP 1536
#define EMPTYK 0xFFFFFFFFFFFFFFFFull

// ---------------- scratch ----------------
__device__ float g_queries[NN * DD];
__device__ float g_qn[NN];
__device__ float g_hn[NN];
__device__ uint32_t g_gensmask[NMASKW];
__device__ int   g_glist[NN];
__device__ int   g_flag[NN];
__device__ unsigned long long g_best[NN];
__device__ int   g_newsend[NN];
__device__ int   g_newrec[NN];
__device__ int   g_ngens;
__device__ int   g_eactive;
__device__ int   g_ncand;

// ---------------- threefry2x32 (JAX-exact) ----------------
__host__ __device__ __forceinline__ void threefry2x32(uint32_t k0, uint32_t k1,
                                                      uint32_t x0, uint32_t x1,
                                                      uint32_t* o0, uint32_t* o1) {
  uint32_t ks2 = k0 ^ k1 ^ 0x1BD11BDAu;
#define ROTL32(v, r) (((v) << (r)) | ((v) >> (32 - (r))))
#define TFRND(r) { x0 += x1; x1 = ROTL32(x1, r); x1 ^= x0; }
  x0 += k0; x1 += k1;
  TFRND(13) TFRND(15) TFRND(26) TFRND(6)
  x0 += k1; x1 += ks2 + 1u;
  TFRND(17) TFRND(29) TFRND(16) TFRND(24)
  x0 += ks2; x1 += k0 + 2u;
  TFRND(13) TFRND(15) TFRND(26) TFRND(6)
  x0 += k0; x1 += k1 + 3u;
  TFRND(17) TFRND(29) TFRND(16) TFRND(24)
  x0 += k1; x1 += ks2 + 4u;
  TFRND(13) TFRND(15) TFRND(26) TFRND(6)
  x0 += ks2; x1 += k0 + 5u;
  *o0 = x0; *o1 = x1;
#undef TFRND
#undef ROTL32
}

__device__ __forceinline__ uint32_t random_bits32(uint32_t k0, uint32_t k1,
                                                  unsigned long long idx) {
  uint32_t o0, o1;
  threefry2x32(k0, k1, (uint32_t)(idx >> 32), (uint32_t)idx, &o0, &o1);
  return o0 ^ o1;
}

__device__ __forceinline__ float u01_from_bits(uint32_t bits) {
  return __uint_as_float((bits >> 9) | 0x3f800000u) - 1.0f;
}

// XLA ErfInv (Giles)
__device__ __forceinline__ float xla_erfinv(float x) {
  float w = -log1pf(-x * x);
  float p;
  if (w < 5.f) {
    w -= 2.5f;
    p = 2.81022636e-08f;
    p = fmaf(p, w, 3.43273939e-07f);
    p = fmaf(p, w, -3.5233877e-06f);
    p = fmaf(p, w, -4.39150654e-06f);
    p = fmaf(p, w, 0.00021858087f);
    p = fmaf(p, w, -0.00125372503f);
    p = fmaf(p, w, -0.00417768164f);
    p = fmaf(p, w, 0.246640727f);
    p = fmaf(p, w, 1.50140941f);
  } else {
    w = sqrtf(w) - 3.f;
    p = -0.000200214257f;
    p = fmaf(p, w, 0.000100950558f);
    p = fmaf(p, w, 0.00134934322f);
    p = fmaf(p, w, -0.00367342844f);
    p = fmaf(p, w, 0.00573950773f);
    p = fmaf(p, w, -0.0076224613f);
    p = fmaf(p, w, 0.00943887047f);
    p = fmaf(p, w, 1.00167406f);
    p = fmaf(p, w, 2.83297682f);
  }
  return p * x;
}

__device__ __forceinline__ unsigned long long enc_key(float v, int j) {
  uint32_t u = __float_as_uint(v);
  u = (u & 0x80000000u) ? ~u : (u | 0x80000000u);
  return ((unsigned long long)u << 32) | (unsigned long long)(0xFFFFFFFFu - (uint32_t)j);
}

__device__ __forceinline__ int warp_incl_scan(int v, int lane) {
#pragma unroll
  for (int d = 1; d < 32; d <<= 1) {
    int o = __shfl_up_sync(0xffffffffu, v, d);
    if (lane >= d) v += o;
  }
  return v;
}

// per-candidate epilogue: cosine clamp + gumbel + warp argmax + atomic
__device__ __forceinline__ void sel_finish(float num, float qn, float hn, float act,
                                           int i, int j, int lane,
                                           uint32_t ks0, uint32_t ks1) {
  float sc = num / (sqrtf(qn * hn) + 1e-8f);
  sc = fminf(fmaxf(sc, -10000.f), 10000.f);
  if (act <= 0.f) sc = NEGV;
  if (j == i) sc = NEGV;
  unsigned long long lin = (unsigned long long)i * NN + (unsigned long long)j;
  uint32_t bits = random_bits32(ks0, ks1, lin);
  float u = fmaxf(TINYF, u01_from_bits(bits) + TINYF);
  float g = -logf(-logf(u));
  unsigned long long key = enc_key(sc + g, j);
#pragma unroll
  for (int d = 16; d > 0; d >>= 1) {
    unsigned long long o = __shfl_xor_sync(0xffffffffu, key, d);
    if (o > key) key = o;
  }
  if (lane == 0) atomicMax(&g_best[i], key);
}

// ---------- Kernel A: prep + generator bitmask ----------
__global__ void __launch_bounds__(512) k_prep(const float* __restrict__ nodes,
                                              const float* __restrict__ Wq,
                                              const float* __restrict__ bq,
                                              const float* __restrict__ Wp,
                                              const float* __restrict__ bp,
                                              const float* __restrict__ active_nodes,
                                              uint32_t kp0, uint32_t kp1) {
  __shared__ __align__(16) float sWq[DD * DD];
  __shared__ float sbq[DD];
  __shared__ float sWp[DD];
  __shared__ int   sgen[64];
  const int tid = threadIdx.x;
  const int warp = tid >> 5, lane = tid & 31;
  {
    const float4* w4 = reinterpret_cast<const float4*>(Wq);
    float4* s4 = reinterpret_cast<float4*>(sWq);
#pragma unroll
    for (int r = 0; r < 2; r++) s4[tid + (r << 9)] = w4[tid + (r << 9)];
    if (tid < DD) { sbq[tid] = bq[tid]; sWp[tid] = Wp[tid]; }
  }
  const int ibase = (blockIdx.x << 6) + (warp << 2);
  float2 n2r[4];
#pragma unroll
  for (int r = 0; r < 4; r++)
    n2r[r] = reinterpret_cast<const float2*>(nodes + (ibase + r) * DD)[lane];
  float anr[4];
#pragma unroll
  for (int r = 0; r < 4; r++) anr[r] = active_nodes[ibase + r];
  __syncthreads();
  const float2 b2 = reinterpret_cast<const float2*>(sbq)[lane];
  const float2 wp2 = reinterpret_cast<const float2*>(sWp)[lane];
  const float bp0 = bp[0];
#pragma unroll
  for (int r = 0; r < 4; r++) {
    const int i = ibase + r;
    const float2 n2 = n2r[r];
    float q0 = b2.x, q1 = b2.y;
#pragma unroll
    for (int k = 0; k < DD; k++) {
      float nk = __shfl_sync(0xffffffffu, (k & 1) ? n2.y : n2.x, k >> 1);
      float2 w = reinterpret_cast<const float2*>(sWq + k * DD)[lane];
      q0 = fmaf(nk, w.x, q0);
      q1 = fmaf(nk, w.y, q1);
    }
    reinterpret_cast<float2*>(g_queries + i * DD)[lane] = make_float2(q0, q1);
    float rq = q0 * q0 + q1 * q1;
    float rh = n2.x * n2.x + n2.y * n2.y;
    float rp = n2.x * wp2.x + n2.y * wp2.y;
#pragma unroll
    for (int d = 16; d > 0; d >>= 1) {
      rq += __shfl_xor_sync(0xffffffffu, rq, d);
      rh += __shfl_xor_sync(0xffffffffu, rh, d);
      rp += __shfl_xor_sync(0xffffffffu, rp, d);
    }
    if (lane == 0) {
      g_qn[i] = rq;
      g_hn[i] = rh;
      float z = rp + bp0;
      float prob = 0.5f * tanhf(0.5f * z) + 0.5f;   // XLA logistic
      uint32_t bits = random_bits32(kp0, kp1, (unsigned long long)i);
      float u = u01_from_bits(bits);
      sgen[(warp << 2) + r] = (u < prob * anr[r]) ? 1 : 0;
      g_best[i] = 0ull;
    }
  }
  __syncthreads();
  if (tid < 2) {
    uint32_t w = 0;
#pragma unroll
    for (int k = 0; k < 32; k++) w |= (uint32_t)sgen[(tid << 5) + k] << k;
    g_gensmask[(blockIdx.x << 1) + tid] = w;
  }
}

// ---------- Kernel B: select — 4-candidate row-sharing ----------
__global__ void __launch_bounds__(SEL_THREADS) k_select(const float* __restrict__ nodes,
                                                        const float* __restrict__ active_nodes,
                                                        uint32_t ks0, uint32_t ks1) {
  __shared__ __align__(16) float sh[TILE_J * TILE_STRIDE];
  __shared__ __align__(16) float qsh[CAND_TILE * DD];
  __shared__ float s_qn[CAND_TILE];
  __shared__ int   s_ii[CAND_TILE];
  __shared__ int   s_glist[CAND_TILE];
  __shared__ int   s_wsum[8];
  const int tid = threadIdx.x;
  const int lane = tid & 31;
  const int wid = tid >> 5;
  const int jj = tid & 127;
  const int grp2 = tid >> 7;

  const uint32_t mw = g_gensmask[tid];
  const int cnt = __popc(mw);
  int incl = warp_incl_scan(cnt, lane);
  if (lane == 31) s_wsum[wid] = incl;
  __syncthreads();
  int wbase = 0, ncand = 0;
#pragma unroll
  for (int w = 0; w < 8; w++) {
    int v = s_wsum[w];
    if (w < wid) wbase += v;
    ncand += v;
  }
  const int mypre = wbase + incl - cnt;

  const int ng = (ncand + CAND_TILE - 1) / CAND_TILE;
  const int total = NCHUNK * ng;
  for (int w = blockIdx.x; w < total; w += gridDim.x) {
    const int chunk = w / ng;
    const int grp = w - chunk * ng;
    const int c0 = grp * CAND_TILE;
    const int jbase = chunk << 7;
    if (cnt) {
      uint32_t m = mw;
      int r = mypre;
      while (m) {
        int b = __ffs((int)m) - 1;
        if (r >= c0 && r < c0 + CAND_TILE) s_glist[r - c0] = (tid << 5) + b;
        m &= m - 1;
        r++;
      }
    }
    __syncthreads();
    {
      const float4* src = reinterpret_cast<const float4*>(nodes + (jbase << 6));
#pragma unroll
      for (int s = 0; s < 8; s++) {
        int idx4 = (s << 8) + tid;
        int row = idx4 >> 4, col4 = idx4 & 15;
        reinterpret_cast<float4*>(sh + row * TILE_STRIDE)[col4] = src[idx4];
      }
    }
    if (tid < CAND_TILE) {
      int idx = c0 + tid;
      int i = (idx < ncand) ? s_glist[tid] : 0;
      s_ii[tid] = i;
      s_qn[tid] = g_qn[i];
    }
#pragma unroll
    for (int s = 0; s < 2; s++) {
      int t4 = (s << 8) + tid;
      int c = t4 >> 4, k4 = t4 & 15;
      int idx = c0 + c;
      float4 qv = (idx < ncand)
          ? reinterpret_cast<const float4*>(g_queries + s_glist[c] * DD)[k4]
          : make_float4(0.f, 0.f, 0.f, 0.f);
      reinterpret_cast<float4*>(qsh + c * DD)[k4] = qv;
    }
    __syncthreads();
    const int j = jbase + jj;
    const float hn = g_hn[j];
    const float act = active_nodes[j];
    const float4* rowf4 = reinterpret_cast<const float4*>(sh + jj * TILE_STRIDE);
    const int clim = (ncand - c0 < CAND_TILE) ? (ncand - c0) : CAND_TILE;
    const int cbeg = grp2 << 4;
    const int cend = (cbeg + 16 < clim) ? cbeg + 16 : clim;
    int c = cbeg;
    // 4-candidate quads: each row float4 loaded ONCE, used by 4 candidates
    for (; c + 3 < cend; c += 4) {
      const float4* qA = reinterpret_cast<const float4*>(qsh + (c + 0) * DD);
      const float4* qB = reinterpret_cast<const float4*>(qsh + (c + 1) * DD);
      const float4* qC = reinterpret_cast<const float4*>(qsh + (c + 2) * DD);
      const float4* qD = reinterpret_cast<const float4*>(qsh + (c + 3) * DD);
      float ax0 = 0.f, ay0 = 0.f, az0 = 0.f, aw0 = 0.f;
      float ax1 = 0.f, ay1 = 0.f, az1 = 0.f, aw1 = 0.f;
      float ax2 = 0.f, ay2 = 0.f, az2 = 0.f, aw2 = 0.f;
      float ax3 = 0.f, ay3 = 0.f, az3 = 0.f, aw3 = 0.f;
#pragma unroll
      for (int kk = 0; kk < 16; kk++) {
        const float4 r = rowf4[kk];
        float4 q;
        q = qA[kk];
        ax0 = fmaf(q.x, r.x, ax0); ay0 = fmaf(q.y, r.y, ay0);
        az0 = fmaf(q.z, r.z, az0); aw0 = fmaf(q.w, r.w, aw0);
        q = qB[kk];
        ax1 = fmaf(q.x, r.x, ax1); ay1 = fmaf(q.y, r.y, ay1);
        az1 = fmaf(q.z, r.z, az1); aw1 = fmaf(q.w, r.w, aw1);
        q = qC[kk];
        ax2 = fmaf(q.x, r.x, ax2); ay2 = fmaf(q.y, r.y, ay2);
        az2 = fmaf(q.z, r.z, az2); aw2 = fmaf(q.w, r.w, aw2);
        q = qD[kk];
        ax3 = fmaf(q.x, r.x, ax3); ay3 = fmaf(q.y, r.y, ay3);
        az3 = fmaf(q.z, r.z, az3); aw3 = fmaf(q.w, r.w, aw3);
      }
      sel_finish((ax0 + az0) + (ay0 + aw0), s_qn[c + 0], hn, act, s_ii[c + 0], j, lane, ks0, ks1);
      sel_finish((ax1 + az1) + (ay1 + aw1), s_qn[c + 1], hn, act, s_ii[c + 1], j, lane, ks0, ks1);
      sel_finish((ax2 + az2) + (ay2 + aw2), s_qn[c + 2], hn, act, s_ii[c + 2], j, lane, ks0, ks1);
      sel_finish((ax3 + az3) + (ay3 + aw3), s_qn[c + 3], hn, act, s_ii[c + 3], j, lane, ks0, ks1);
    }
    // scalar remainder
    for (; c < cend; c++) {
      const float4* qf4 = reinterpret_cast<const float4*>(qsh + c * DD);
      float ax = 0.f, ay = 0.f, az = 0.f, aw = 0.f;
#pragma unroll
      for (int kk = 0; kk < 16; kk++) {
        float4 r = rowf4[kk];
        float4 q = qf4[kk];
        ax = fmaf(q.x, r.x, ax);
        ay = fmaf(q.y, r.y, ay);
        az = fmaf(q.z, r.z, az);
        aw = fmaf(q.w, r.w, aw);
      }
      sel_finish((ax + az) + (ay + aw), s_qn[c], hn, act, s_ii[c], j, lane, ks0, ks1);
    }
    __syncthreads();
  }
}

// ---- Kernel C: e_active + glist + exist-hash + compaction, ONE block ----
__global__ void __launch_bounds__(1024) k_cc(const float* __restrict__ active_edges,
                                             const int* __restrict__ senders,
                                             const int* __restrict__ receivers) {
  __shared__ unsigned long long hkey[HASH_SZ];
  __shared__ int   hcid[HASH_SZ];
  __shared__ float swF[32];
  __shared__ int   swA[32];
  __shared__ int   pre[33];
  const int tid = threadIdx.x;  // 1024
  const int lane = tid & 31, wid = tid >> 5;

  {
    const float4* ae4 = reinterpret_cast<const float4*>(active_edges);
    float s = 0.f;
#pragma unroll
    for (int r = 0; r < 4; r++) {
      float4 v = ae4[tid + (r << 10)];
      s += v.x + v.y + v.z + v.w;
    }
#pragma unroll
    for (int d = 16; d > 0; d >>= 1) s += __shfl_xor_sync(0xffffffffu, s, d);
    if (lane == 0) swF[wid] = s;
  }
  const uint32_t mw = (tid < NMASKW) ? g_gensmask[tid] : 0u;
  const int cnt = __popc(mw);
  int incl = warp_incl_scan(cnt, lane);
  if (lane == 31) swA[wid] = incl;
  __syncthreads();
  if (tid == 0) {
    pre[0] = 0;
#pragma unroll
    for (int w = 0; w < 32; w++) pre[w + 1] = pre[w] + swA[w];
    g_ncand = pre[32];
    float t = 0.f;
#pragma unroll
    for (int w = 0; w < 32; w++) t += swF[w];
    g_eactive = (int)t;
  }
  __syncthreads();
  const int ncand = pre[32];
  {
    int r = pre[wid] + incl - cnt;
    uint32_t m = mw;
    while (m) {
      int b = __ffs((int)m) - 1;
      g_glist[r] = (tid << 5) + b;
      g_flag[r] = 1;
      m &= m - 1;
      r++;
    }
  }
  __syncthreads();

  if (ncand <= HASH_CAP) {
#pragma unroll
    for (int r = 0; r < HASH_SZ / 1024; r++) hkey[tid + (r << 10)] = EMPTYK;
    __syncthreads();
    for (int c = tid; c < ncand; c += 1024) {
      int i = g_glist[c];
      unsigned long long b = g_best[i];
      uint32_t sel = 0xFFFFFFFFu - (uint32_t)(b & 0xFFFFFFFFull);
      unsigned long long key = ((unsigned long long)(uint32_t)i << 32) | sel;
      uint32_t h = (uint32_t)((key * 0x9E3779B97F4A7C15ull) >> 40) & (HASH_SZ - 1);
      while (true) {
        unsigned long long prev = atomicCAS(&hkey[h], EMPTYK, key);
        if (prev == EMPTYK) { hcid[h] = c; break; }
        h = (h + 1) & (HASH_SZ - 1);
      }
    }
    __syncthreads();
    const int4* s4 = reinterpret_cast<const int4*>(senders);
    const int4* r4 = reinterpret_cast<const int4*>(receivers);
#pragma unroll
    for (int r = 0; r < EE / 4 / 1024; r++) {
      int idx4 = tid + (r << 10);
      int4 sv = s4[idx4];
      int4 rv = r4[idx4];
      const int ss[4] = {sv.x, sv.y, sv.z, sv.w};
      const int rr[4] = {rv.x, rv.y, rv.z, rv.w};
#pragma unroll
      for (int q = 0; q < 4; q++) {
        unsigned long long key =
            ((unsigned long long)(uint32_t)ss[q] << 32) | (uint32_t)rr[q];
        uint32_t h = (uint32_t)((key * 0x9E3779B97F4A7C15ull) >> 40) & (HASH_SZ - 1);
        while (true) {
          unsigned long long k = hkey[h];
          if (k == EMPTYK) break;
          if (k == key) { g_flag[hcid[h]] = 0; break; }
          h = (h + 1) & (HASH_SZ - 1);
        }
      }
    }
    __syncthreads();
  } else {
    for (int c = tid; c < ncand; c += 1024) {
      int i = g_glist[c];
      unsigned long long b = g_best[i];
      uint32_t sel = 0xFFFFFFFFu - (uint32_t)(b & 0xFFFFFFFFull);
      int found = 0;
      for (int e = 0; e < EE; e++)
        found |= (senders[e] == i && (uint32_t)receivers[e] == sel);
      if (found) g_flag[c] = 0;
    }
    __syncthreads();
  }

  int flags[8];
  int ccnt = 0;
#pragma unroll
  for (int r = 0; r < 8; r++) {
    int c = tid * 8 + r;
    flags[r] = (c < ncand) ? g_flag[c] : 0;
    ccnt += flags[r];
  }
  int cincl = warp_incl_scan(ccnt, lane);
  if (lane == 31) swA[wid] = cincl;
  __syncthreads();
  if (tid == 0) {
    pre[0] = 0;
#pragma unroll
    for (int w = 0; w < 32; w++) pre[w + 1] = pre[w] + swA[w];
    int total = pre[32];
    int allowed = EE - g_eactive - 1;
    int n = total < 0 ? 0 : total;
    if (n > allowed) n = allowed;
    g_ngens = n;
  }
  __syncthreads();
  int off = pre[wid] + cincl - ccnt;
#pragma unroll
  for (int r = 0; r < 8; r++) {
    int c = tid * 8 + r;
    if (flags[r]) {
      int i = g_glist[c];
      unsigned long long b = g_best[i];
      g_newsend[off] = i;
      g_newrec[off] = (int)(0xFFFFFFFFu - (uint32_t)(b & 0xFFFFFFFFull));
      off++;
    }
  }
}

// ---------- Kernel D: output writer — 1 float4/thread, full occupancy ----------
// Layout: [ new_edges (E*D f32) | nsend (E) | nrec (E) | naedges (E) ]
__global__ void __launch_bounds__(256) k_out(const float* __restrict__ edges,
                                             const int* __restrict__ senders,
                                             const int* __restrict__ receivers,
                                             float4* __restrict__ out,
                                             uint32_t ke0, uint32_t ke1, int out_size) {
  const int idx4 = blockIdx.x * 256 + threadIdx.x;
  const int base = idx4 << 2;
  if (base >= out_size) return;
  const int ngen = g_ngens;
  const int ea = g_eactive;
  const int T1 = EE * DD;
  float4 v;
  if (base < T1) {
    v = reinterpret_cast<const float4*>(edges)[idx4];
    int e = base >> 6;
    if (e >= ea && e < ea + ngen) {
      float* vp = reinterpret_cast<float*>(&v);
#pragma unroll
      for (int cmp = 0; cmp < 4; cmp++) {
        uint32_t bits = random_bits32(ke0, ke1, (unsigned long long)(base + cmp));
        float u01 = u01_from_bits(bits);
        const float lo = -0.99999994f;
        float uu = fmaxf(lo, fmaf(u01, 2.0f, lo));
        vp[cmp] += 1.41421356f * xla_erfinv(uu);
      }
    }
  } else if (base < T1 + EE) {
    float* vp = reinterpret_cast<float*>(&v);
#pragma unroll
    for (int cmp = 0; cmp < 4; cmp++) {
      int j = base + cmp - T1;
      float x;
      if (j < ea)             x = (float)senders[j];
      else if (j < ea + ngen) x = (float)g_newsend[j - ea];
      else                    x = (float)(NN - 1);
      vp[cmp] = x;
    }
  } else if (base < T1 + 2 * EE) {
    float* vp = reinterpret_cast<float*>(&v);
#pragma unroll
    for (int cmp = 0; cmp < 4; cmp++) {
      int j = base + cmp - T1 - EE;
      float x;
      if (j < ea)             x = (float)receivers[j];
      else if (j < ea + ngen) x = (float)g_newrec[j - ea];
      else                    x = (float)(NN - 1);
      vp[cmp] = x;
    }
  } else {
    float* vp = reinterpret_cast<float*>(&v);
#pragma unroll
    for (int cmp = 0; cmp < 4; cmp++) {
      int j = base + cmp - T1 - 2 * EE;
      vp[cmp] = (j < ea + ngen && j >= 0) ? 1.0f : 0.0f;
    }
  }
  if (base + 4 <= out_size) {
    out[idx4] = v;
  } else {
    float* vp = reinterpret_cast<float*>(&v);
    float* os = reinterpret_cast<float*>(out);
    for (int cmp = 0; cmp < out_size - base; cmp++) os[base + cmp] = vp[cmp];
  }
}

// ---------------- host ----------------
extern "C" void kernel_launch(void* const* d_in, const int* in_sizes, int n_in,
                              void* d_out, int out_size) {
  const float* nodes        = (const float*)d_in[0];
  const float* edges        = (const float*)d_in[1];
  const int*   receivers    = (const int*)d_in[2];
  const int*   senders      = (const int*)d_in[3];
  const float* active_nodes = (const float*)d_in[4];
  const float* active_edges = (const float*)d_in[5];
  const float* Wq           = (const float*)d_in[6];
  const float* bq           = (const float*)d_in[7];
  const float* Wp           = (const float*)d_in[8];
  const float* bp           = (const float*)d_in[9];
  (void)in_sizes; (void)n_in;

  const uint32_t K0 = 0u, K1 = 42u;
  uint32_t kp0, kp1, ke0, ke1, ks0, ks1;
  threefry2x32(K0, K1, 0u, 0u, &kp0, &kp1);  // key_prob
  threefry2x32(K0, K1, 0u, 1u, &ke0, &ke1);  // key_edges
  threefry2x32(K0, K1, 0u, 2u, &ks0, &ks1);  // key_samp

  k_prep<<<NN / 64, 512>>>(nodes, Wq, bq, Wp, bp, active_nodes, kp0, kp1);
  k_select<<<592, SEL_THREADS>>>(nodes, active_nodes, ks0, ks1);
  k_cc<<<1, 1024>>>(active_edges, senders, receivers);

  int n4 = (out_size + 3) >> 2;
  int blocks = (n4 + 255) / 256;
  k_out<<<blocks, 256>>>(edges, senders, receivers, (float4*)d_out, ke0, ke1, out_size);
}